// round 1
// baseline (speedup 1.0000x reference)
#include <cuda_runtime.h>
#include <float.h>
#include <math.h>

#define B 8
#define N 2048
#define PTS (B*N)          // 16384
#define KNN 20
#define FEAT 512
#define OMAX 256
#define EPSV 1e-5f

// ---------------- scratch (static device allocations) ----------------
__device__ float d_dist[(size_t)PTS * N];        // 134 MB
__device__ float d_xx[PTS];
__device__ int   d_idx[PTS * KNN];
__device__ float d_feat[(size_t)PTS * FEAT];     // concat output of 4 layers
__device__ float d_s[(size_t)PTS * OMAX];
__device__ float d_t[(size_t)PTS * OMAX];
__device__ float d_maxg[(size_t)PTS * OMAX];
__device__ float d_ming[(size_t)PTS * OMAX];
__device__ float d_acc_s[OMAX], d_acc_s2[OMAX], d_acc_cr[OMAX], d_acc_t[OMAX], d_acc_t2[OMAX];
__device__ float d_rho[OMAX], d_shift[OMAX];
__device__ float d_poolmax[B * 8 * FEAT], d_poolsum[B * 8 * FEAT];

// ---------------- kernels ----------------

__global__ void zero_acc_kernel() {
    int i = threadIdx.x;
    if (i < OMAX) {
        d_acc_s[i] = 0.f; d_acc_s2[i] = 0.f; d_acc_cr[i] = 0.f;
        d_acc_t[i] = 0.f; d_acc_t2[i] = 0.f;
    }
}

// squared norms per point
__global__ void xx_kernel(const float* x, int stride, int off, int C) {
    const float* xp = x ? x : d_feat;
    int p = blockIdx.x * blockDim.x + threadIdx.x;
    if (p >= PTS) return;
    const float* r = xp + (size_t)p * stride + off;
    float s = 0.f;
    for (int c = 0; c < C; c++) { float v = r[c]; s = fmaf(v, v, s); }
    d_xx[p] = s;
}

// dist[b,n,m] = xx[n] + xx[m] - 2 * dot(x_n, x_m); 64x64 tile, 4x4 per thread
__global__ void dist_kernel(const float* x, int stride, int off, int C) {
    const float* xp = x ? x : d_feat;
    int b = blockIdx.x;
    int n0 = blockIdx.y * 64;
    int m0 = blockIdx.z * 64;
    __shared__ float As[64][9];
    __shared__ float Bs[64][9];
    int tid = threadIdx.x;
    int tx = tid & 15, ty = tid >> 4;
    float acc[4][4];
#pragma unroll
    for (int i = 0; i < 4; i++)
#pragma unroll
        for (int j = 0; j < 4; j++) acc[i][j] = 0.f;

    for (int c0 = 0; c0 < C; c0 += 8) {
        for (int l = tid; l < 512; l += 256) {
            int r = l >> 3, cc = l & 7;
            int c = c0 + cc;
            float av = 0.f, bv = 0.f;
            if (c < C) {
                av = xp[(size_t)(b * N + n0 + r) * stride + off + c];
                bv = xp[(size_t)(b * N + m0 + r) * stride + off + c];
            }
            As[r][cc] = av;
            Bs[r][cc] = bv;
        }
        __syncthreads();
#pragma unroll
        for (int kk = 0; kk < 8; kk++) {
            float a[4], bb[4];
#pragma unroll
            for (int i = 0; i < 4; i++) { a[i] = As[ty + 16 * i][kk]; bb[i] = Bs[tx + 16 * i][kk]; }
#pragma unroll
            for (int i = 0; i < 4; i++)
#pragma unroll
                for (int j = 0; j < 4; j++) acc[i][j] = fmaf(a[i], bb[j], acc[i][j]);
        }
        __syncthreads();
    }
#pragma unroll
    for (int i = 0; i < 4; i++) {
        int n = n0 + ty + 16 * i;
        float xn = d_xx[b * N + n];
#pragma unroll
        for (int j = 0; j < 4; j++) {
            int m = m0 + tx + 16 * j;
            d_dist[(size_t)(b * N + n) * N + m] = xn + d_xx[b * N + m] - 2.f * acc[i][j];
        }
    }
}

// per-row top-KNN (smallest dist, ties -> lower index, matching jax top_k(-dist))
__global__ void select_kernel() {
    int pt = blockIdx.x;
    __shared__ float row[N];
    __shared__ float rv[256];
    __shared__ int   ri[256];
    int tid = threadIdx.x;
    const float* dr = d_dist + (size_t)pt * N;
    for (int i = tid; i < N; i += 256) row[i] = dr[i];
    __syncthreads();
    for (int sel = 0; sel < KNN; sel++) {
        float bv = FLT_MAX; int bi = N;
        for (int i = tid; i < N; i += 256) {
            float v = row[i];
            if (v < bv) { bv = v; bi = i; }
        }
        rv[tid] = bv; ri[tid] = bi;
        __syncthreads();
        for (int s = 128; s > 0; s >>= 1) {
            if (tid < s) {
                float ov = rv[tid + s]; int oi = ri[tid + s];
                if (ov < rv[tid] || (ov == rv[tid] && oi < ri[tid])) { rv[tid] = ov; ri[tid] = oi; }
            }
            __syncthreads();
        }
        if (tid == 0) {
            d_idx[pt * KNN + sel] = ri[0];
            row[ri[0]] = FLT_MAX;
        }
        __syncthreads();
    }
}

// s = W1 . x ; t = (W2-W1) . x ; also accumulate sum(t), sum(t^2) per channel
// blockDim = O, 32 points per block
__global__ void st_kernel(const float* x, int stride, int off, int C, int O, const float* W) {
    const float* xp = x ? x : d_feat;
    __shared__ float xs[32 * 128];
    int pt0 = blockIdx.x * 32;
    int tid = threadIdx.x;
    for (int i = tid; i < 32 * C; i += O) {
        int p = i / C, c = i - p * C;
        xs[i] = xp[(size_t)(pt0 + p) * stride + off + c];
    }
    __syncthreads();
    float as[32], at[32];
#pragma unroll
    for (int p = 0; p < 32; p++) { as[p] = 0.f; at[p] = 0.f; }
    const float* wr = W + (size_t)tid * 2 * C;
    for (int c = 0; c < C; c++) {
        float w1 = wr[c];
        float wd = wr[C + c] - w1;
#pragma unroll
        for (int p = 0; p < 32; p++) {
            float xv = xs[p * C + c];
            as[p] = fmaf(w1, xv, as[p]);
            at[p] = fmaf(wd, xv, at[p]);
        }
    }
    float ts = 0.f, ts2 = 0.f;
#pragma unroll
    for (int p = 0; p < 32; p++) {
        size_t e = (size_t)(pt0 + p) * O + tid;
        d_s[e] = as[p];
        d_t[e] = at[p];
        ts += at[p];
        ts2 = fmaf(at[p], at[p], ts2);
    }
    atomicAdd(&d_acc_t[tid], ts);
    atomicAdd(&d_acc_t2[tid], ts2);
}

// gather: per (point, channel) compute sum/max/min over k of s[idx], + BN stat partials
// block = 256 threads = 8 warps; warp -> (o-chunk, point substrip); 64 points per block
__global__ void gather_kernel(int O) {
    int w = threadIdx.x >> 5, lane = threadIdx.x & 31;
    int nchunks = O >> 5;          // 2, 4, or 8
    int oc = w & (nchunks - 1);
    int sub = w / nchunks;
    int nsub = 8 / nchunks;
    int o = (oc << 5) + lane;
    int pt0 = blockIdx.x * 64;
    float sum = 0.f, sq = 0.f, cross = 0.f;
    for (int p = sub; p < 64; p += nsub) {
        int pt = pt0 + p;
        int b = pt >> 11;                    // pt / N
        const int* ip = d_idx + pt * KNN;
        float psum = 0.f, psq = 0.f, pmx = -FLT_MAX, pmn = FLT_MAX;
#pragma unroll
        for (int k = 0; k < KNN; k++) {
            int m = ip[k];
            float v = d_s[(size_t)((b << 11) + m) * O + o];
            psum += v;
            psq = fmaf(v, v, psq);
            pmx = fmaxf(pmx, v);
            pmn = fminf(pmn, v);
        }
        float tv = d_t[(size_t)pt * O + o];
        sum += psum;
        sq += psq;
        cross = fmaf(tv, psum, cross);
        d_maxg[(size_t)pt * O + o] = pmx;
        d_ming[(size_t)pt * O + o] = pmn;
    }
    atomicAdd(&d_acc_s[o], sum);
    atomicAdd(&d_acc_s2[o], sq);
    atomicAdd(&d_acc_cr[o], cross);
}

// finalize BN params: mean/var over (B,N,k) per channel -> rho, shift
__global__ void bn_kernel(int O, const float* gamma, const float* beta) {
    int o = threadIdx.x;
    if (o >= O) return;
    const float cnt = (float)PTS * (float)KNN;
    float mean = (d_acc_s[o] + (float)KNN * d_acc_t[o]) / cnt;
    float e2 = (d_acc_s2[o] + 2.f * d_acc_cr[o] + (float)KNN * d_acc_t2[o]) / cnt;
    float var = e2 - mean * mean;
    float inv = rsqrtf(var + EPSV);
    float rho = gamma[o] * inv;
    d_rho[o] = rho;
    d_shift[o] = beta[o] - mean * rho;
}

// apply BN + relu + max_k (monotone: use maxg if rho>=0 else ming), write into feat
__global__ void apply_kernel(int O, int off) {
    int e = blockIdx.x * 256 + threadIdx.x;
    if (e >= PTS * O) return;
    int o = e % O;
    int pt = e / O;
    float r = d_rho[o];
    float base = d_t[e] + (r >= 0.f ? d_maxg[e] : d_ming[e]);
    float res = fmaf(r, base, d_shift[o]);
    d_feat[(size_t)pt * FEAT + off + o] = fmaxf(res, 0.f);
}

// per-(b, strip) partial max/sum over n
__global__ void pool_kernel() {
    int b = blockIdx.x, st = blockIdx.y;
    int c = threadIdx.x;          // 512 threads
    float mx = -FLT_MAX, sm = 0.f;
    int n0 = st * 256;
    for (int n = n0; n < n0 + 256; n++) {
        float v = d_feat[(size_t)(b * N + n) * FEAT + c];
        mx = fmaxf(mx, v);
        sm += v;
    }
    d_poolmax[(b * 8 + st) * FEAT + c] = mx;
    d_poolsum[(b * 8 + st) * FEAT + c] = sm;
}

// head: combine pooling, fc1 + LN + relu, fc2 + LN. One block per batch.
__global__ void head_kernel(const float* fc1_w, const float* fc1_b,
                            const float* ln1_g, const float* ln1_b,
                            const float* fc2_w, const float* fc2_b,
                            const float* ln2_g, const float* ln2_b,
                            float* out) {
    __shared__ float g[1024];
    __shared__ float h[512];
    __shared__ float red[256];
    __shared__ float red2[256];
    int b = blockIdx.x, tid = threadIdx.x;
    for (int c = tid; c < 512; c += 256) {
        float mx = -FLT_MAX, sm = 0.f;
        for (int st = 0; st < 8; st++) {
            mx = fmaxf(mx, d_poolmax[(b * 8 + st) * FEAT + c]);
            sm += d_poolsum[(b * 8 + st) * FEAT + c];
        }
        g[c] = mx;
        g[512 + c] = sm * (1.f / (float)N);
    }
    __syncthreads();
    for (int j = tid; j < 512; j += 256) {
        float acc = fc1_b[j];
        const float* wr = fc1_w + (size_t)j * 1024;
        for (int i = 0; i < 1024; i++) acc = fmaf(g[i], wr[i], acc);
        h[j] = acc;
    }
    __syncthreads();
    // LN1 over 512
    {
        float a = h[tid], bb = h[tid + 256];
        red[tid] = a + bb;
        red2[tid] = a * a + bb * bb;
    }
    __syncthreads();
    for (int s = 128; s > 0; s >>= 1) {
        if (tid < s) { red[tid] += red[tid + s]; red2[tid] += red2[tid + s]; }
        __syncthreads();
    }
    float mu = red[0] * (1.f / 512.f);
    float var = red2[0] * (1.f / 512.f) - mu * mu;
    float inv = rsqrtf(var + EPSV);
    __syncthreads();
    for (int j = tid; j < 512; j += 256)
        h[j] = fmaxf(0.f, (h[j] - mu) * inv * ln1_g[j] + ln1_b[j]);
    __syncthreads();
    // fc2: one output per thread
    float z = fc2_b[tid];
    {
        const float* wr = fc2_w + (size_t)tid * 512;
        for (int i = 0; i < 512; i++) z = fmaf(h[i], wr[i], z);
    }
    // LN2 over 256
    red[tid] = z;
    red2[tid] = z * z;
    __syncthreads();
    for (int s = 128; s > 0; s >>= 1) {
        if (tid < s) { red[tid] += red[tid + s]; red2[tid] += red2[tid + s]; }
        __syncthreads();
    }
    float mu2 = red[0] * (1.f / 256.f);
    float var2 = red2[0] * (1.f / 256.f) - mu2 * mu2;
    float inv2 = rsqrtf(var2 + EPSV);
    out[b * 256 + tid] = (z - mu2) * inv2 * ln2_g[tid] + ln2_b[tid];
}

// ---------------- launch ----------------

extern "C" void kernel_launch(void* const* d_in, const int* in_sizes, int n_in,
                              void* d_out, int out_size) {
    (void)in_sizes; (void)n_in; (void)out_size;
    const float* points = (const float*)d_in[0];
    const float* Wl[4]  = {(const float*)d_in[1], (const float*)d_in[4],
                           (const float*)d_in[7], (const float*)d_in[10]};
    const float* gl[4]  = {(const float*)d_in[2], (const float*)d_in[5],
                           (const float*)d_in[8], (const float*)d_in[11]};
    const float* bl[4]  = {(const float*)d_in[3], (const float*)d_in[6],
                           (const float*)d_in[9], (const float*)d_in[12]};
    const float* fc1_w = (const float*)d_in[13];
    const float* fc1_b = (const float*)d_in[14];
    const float* ln1_g = (const float*)d_in[15];
    const float* ln1_b = (const float*)d_in[16];
    const float* fc2_w = (const float*)d_in[17];
    const float* fc2_b = (const float*)d_in[18];
    const float* ln2_g = (const float*)d_in[19];
    const float* ln2_b = (const float*)d_in[20];

    const int Cs[4]     = {3, 64, 64, 128};
    const int Os[4]     = {64, 64, 128, 256};
    const int offin[4]  = {0, 0, 64, 128};
    const int offout[4] = {0, 64, 128, 256};

    for (int l = 0; l < 4; l++) {
        const float* xin = (l == 0) ? points : nullptr;   // nullptr -> d_feat inside kernels
        int stride = (l == 0) ? 3 : FEAT;
        int C = Cs[l], O = Os[l];

        zero_acc_kernel<<<1, 256>>>();
        xx_kernel<<<(PTS + 255) / 256, 256>>>(xin, stride, offin[l], C);
        dist_kernel<<<dim3(B, N / 64, N / 64), 256>>>(xin, stride, offin[l], C);
        select_kernel<<<PTS, 256>>>();
        st_kernel<<<PTS / 32, O>>>(xin, stride, offin[l], C, O, Wl[l]);
        gather_kernel<<<PTS / 64, 256>>>(O);
        bn_kernel<<<1, O>>>(O, gl[l], bl[l]);
        apply_kernel<<<(PTS * O + 255) / 256, 256>>>(O, offout[l]);
    }

    pool_kernel<<<dim3(B, 8), 512>>>();
    head_kernel<<<B, 256>>>(fc1_w, fc1_b, ln1_g, ln1_b,
                            fc2_w, fc2_b, ln2_g, ln2_b, (float*)d_out);
}

// round 2
// speedup vs baseline: 1.6750x; 1.6750x over previous
#include <cuda_runtime.h>
#include <float.h>
#include <math.h>

#define B 8
#define N 2048
#define PTS (B*N)          // 16384
#define KNN 20
#define FEAT 512
#define OMAX 256
#define EPSV 1e-5f

// ---------------- scratch (static device allocations) ----------------
__device__ float d_dist[(size_t)PTS * N];        // 134 MB
__device__ float d_xx[PTS];
__device__ int   d_idx[PTS * KNN];
__device__ float d_feat[(size_t)PTS * FEAT];     // concat output of 4 layers
__device__ float d_s[(size_t)PTS * OMAX];
__device__ float d_t[(size_t)PTS * OMAX];
__device__ float d_maxg[(size_t)PTS * OMAX];
__device__ float d_ming[(size_t)PTS * OMAX];
__device__ float d_acc_s[OMAX], d_acc_s2[OMAX], d_acc_cr[OMAX], d_acc_t[OMAX], d_acc_t2[OMAX];
__device__ float d_rho[OMAX], d_shift[OMAX];
__device__ float d_poolmax[B * 8 * FEAT], d_poolsum[B * 8 * FEAT];

// ---------------- kernels ----------------

__global__ void zero_acc_kernel() {
    int i = threadIdx.x;
    if (i < OMAX) {
        d_acc_s[i] = 0.f; d_acc_s2[i] = 0.f; d_acc_cr[i] = 0.f;
        d_acc_t[i] = 0.f; d_acc_t2[i] = 0.f;
    }
}

// squared norms per point
__global__ void xx_kernel(const float* x, int stride, int off, int C) {
    const float* xp = x ? x : d_feat;
    int p = blockIdx.x * blockDim.x + threadIdx.x;
    if (p >= PTS) return;
    const float* r = xp + (size_t)p * stride + off;
    float s = 0.f;
    for (int c = 0; c < C; c++) { float v = r[c]; s = fmaf(v, v, s); }
    d_xx[p] = s;
}

// dist[b,n,m] = xx[n] + xx[m] - 2 * dot(x_n, x_m); 128x128 tile, 8x8 per thread, k-panel 16
__global__ void dist_kernel(const float* __restrict__ x, int stride, int off, int C) {
    const float* xp = x ? x : d_feat;
    int b = blockIdx.x;
    int n0 = blockIdx.y * 128;
    int m0 = blockIdx.z * 128;
    __shared__ float As[128][17];
    __shared__ float Bs[128][17];
    int tid = threadIdx.x;
    int tx = tid & 15, ty = tid >> 4;
    float acc[8][8];
#pragma unroll
    for (int i = 0; i < 8; i++)
#pragma unroll
        for (int j = 0; j < 8; j++) acc[i][j] = 0.f;

    for (int c0 = 0; c0 < C; c0 += 16) {
        for (int l = tid; l < 2048; l += 256) {
            int r = l >> 4, cc = l & 15;
            int c = c0 + cc;
            float av = 0.f, bv = 0.f;
            if (c < C) {
                av = xp[(size_t)(b * N + n0 + r) * stride + off + c];
                bv = xp[(size_t)(b * N + m0 + r) * stride + off + c];
            }
            As[r][cc] = av;
            Bs[r][cc] = bv;
        }
        __syncthreads();
#pragma unroll
        for (int kk = 0; kk < 16; kk++) {
            float a[8], bb[8];
#pragma unroll
            for (int i = 0; i < 8; i++) { a[i] = As[ty + 16 * i][kk]; bb[i] = Bs[tx + 16 * i][kk]; }
#pragma unroll
            for (int i = 0; i < 8; i++)
#pragma unroll
                for (int j = 0; j < 8; j++) acc[i][j] = fmaf(a[i], bb[j], acc[i][j]);
        }
        __syncthreads();
    }
#pragma unroll
    for (int i = 0; i < 8; i++) {
        int n = n0 + ty + 16 * i;
        float xn = d_xx[b * N + n];
#pragma unroll
        for (int j = 0; j < 8; j++) {
            int m = m0 + tx + 16 * j;
            d_dist[(size_t)(b * N + n) * N + m] = xn + d_xx[b * N + m] - 2.f * acc[i][j];
        }
    }
}

// per-row top-KNN: warp per row, lane owns interleaved strip {lane+32m},
// cached per-lane argmin + shfl argmin with (value, index) lexicographic order
// (matches jax top_k(-dist): smallest dist, ties -> lower index)
__global__ void select_kernel() {
    __shared__ float rows[4][N];
    int warp = threadIdx.x >> 5, lane = threadIdx.x & 31;
    int pt = blockIdx.x * 4 + warp;
    float* row = rows[warp];
    const float4* dr4 = (const float4*)(d_dist + (size_t)pt * N);
    float4* row4 = (float4*)row;
#pragma unroll
    for (int i = lane; i < N / 4; i += 32) row4[i] = dr4[i];
    __syncwarp();

    float bv = FLT_MAX; int bi = 0;
#pragma unroll 8
    for (int m = 0; m < 64; m++) {
        int i = lane + 32 * m;
        float v = row[i];
        if (v < bv) { bv = v; bi = i; }
    }
    int* ip = d_idx + pt * KNN;
    for (int sel = 0; sel < KNN; sel++) {
        float mv = bv; int mi = bi;
#pragma unroll
        for (int s = 16; s > 0; s >>= 1) {
            float ov = __shfl_xor_sync(0xffffffff, mv, s);
            int   oi = __shfl_xor_sync(0xffffffff, mi, s);
            if (ov < mv || (ov == mv && oi < mi)) { mv = ov; mi = oi; }
        }
        if (lane == 0) ip[sel] = mi;
        if ((mi & 31) == lane) {
            row[mi] = FLT_MAX;
            bv = FLT_MAX; bi = 0;
#pragma unroll 8
            for (int m = 0; m < 64; m++) {
                int i = lane + 32 * m;
                float v = row[i];
                if (v < bv) { bv = v; bi = i; }
            }
        }
        __syncwarp();
    }
}

// s = W1 . x ; t = (W2-W1) . x ; also accumulate sum(t), sum(t^2) per channel
// blockDim = O, 32 points per block
__global__ void st_kernel(const float* x, int stride, int off, int C, int O, const float* W) {
    const float* xp = x ? x : d_feat;
    __shared__ float xs[32 * 128];
    int pt0 = blockIdx.x * 32;
    int tid = threadIdx.x;
    for (int i = tid; i < 32 * C; i += O) {
        int p = i / C, c = i - p * C;
        xs[i] = xp[(size_t)(pt0 + p) * stride + off + c];
    }
    __syncthreads();
    float as[32], at[32];
#pragma unroll
    for (int p = 0; p < 32; p++) { as[p] = 0.f; at[p] = 0.f; }
    const float* wr = W + (size_t)tid * 2 * C;
    for (int c = 0; c < C; c++) {
        float w1 = wr[c];
        float wd = wr[C + c] - w1;
#pragma unroll
        for (int p = 0; p < 32; p++) {
            float xv = xs[p * C + c];
            as[p] = fmaf(w1, xv, as[p]);
            at[p] = fmaf(wd, xv, at[p]);
        }
    }
    float ts = 0.f, ts2 = 0.f;
#pragma unroll
    for (int p = 0; p < 32; p++) {
        size_t e = (size_t)(pt0 + p) * O + tid;
        d_s[e] = as[p];
        d_t[e] = at[p];
        ts += at[p];
        ts2 = fmaf(at[p], at[p], ts2);
    }
    atomicAdd(&d_acc_t[tid], ts);
    atomicAdd(&d_acc_t2[tid], ts2);
}

// gather: per (point, channel) compute sum/max/min over k of s[idx], + BN stat partials
__global__ void gather_kernel(int O) {
    int w = threadIdx.x >> 5, lane = threadIdx.x & 31;
    int nchunks = O >> 5;          // 2, 4, or 8
    int oc = w & (nchunks - 1);
    int sub = w / nchunks;
    int nsub = 8 / nchunks;
    int o = (oc << 5) + lane;
    int pt0 = blockIdx.x * 64;
    float sum = 0.f, sq = 0.f, cross = 0.f;
    for (int p = sub; p < 64; p += nsub) {
        int pt = pt0 + p;
        int b = pt >> 11;                    // pt / N
        const int* ip = d_idx + pt * KNN;
        float psum = 0.f, psq = 0.f, pmx = -FLT_MAX, pmn = FLT_MAX;
#pragma unroll
        for (int k = 0; k < KNN; k++) {
            int m = ip[k];
            float v = d_s[(size_t)((b << 11) + m) * O + o];
            psum += v;
            psq = fmaf(v, v, psq);
            pmx = fmaxf(pmx, v);
            pmn = fminf(pmn, v);
        }
        float tv = d_t[(size_t)pt * O + o];
        sum += psum;
        sq += psq;
        cross = fmaf(tv, psum, cross);
        d_maxg[(size_t)pt * O + o] = pmx;
        d_ming[(size_t)pt * O + o] = pmn;
    }
    atomicAdd(&d_acc_s[o], sum);
    atomicAdd(&d_acc_s2[o], sq);
    atomicAdd(&d_acc_cr[o], cross);
}

// finalize BN params: mean/var over (B,N,k) per channel -> rho, shift
__global__ void bn_kernel(int O, const float* gamma, const float* beta) {
    int o = threadIdx.x;
    if (o >= O) return;
    const float cnt = (float)PTS * (float)KNN;
    float mean = (d_acc_s[o] + (float)KNN * d_acc_t[o]) / cnt;
    float e2 = (d_acc_s2[o] + 2.f * d_acc_cr[o] + (float)KNN * d_acc_t2[o]) / cnt;
    float var = e2 - mean * mean;
    float inv = rsqrtf(var + EPSV);
    float rho = gamma[o] * inv;
    d_rho[o] = rho;
    d_shift[o] = beta[o] - mean * rho;
}

// apply BN + relu + max_k (monotone: use maxg if rho>=0 else ming), write into feat
__global__ void apply_kernel(int O, int off) {
    int e = blockIdx.x * 256 + threadIdx.x;
    if (e >= PTS * O) return;
    int o = e % O;
    int pt = e / O;
    float r = d_rho[o];
    float base = d_t[e] + (r >= 0.f ? d_maxg[e] : d_ming[e]);
    float res = fmaf(r, base, d_shift[o]);
    d_feat[(size_t)pt * FEAT + off + o] = fmaxf(res, 0.f);
}

// per-(b, strip) partial max/sum over n
__global__ void pool_kernel() {
    int b = blockIdx.x, st = blockIdx.y;
    int c = threadIdx.x;          // 512 threads
    float mx = -FLT_MAX, sm = 0.f;
    int n0 = st * 256;
    for (int n = n0; n < n0 + 256; n++) {
        float v = d_feat[(size_t)(b * N + n) * FEAT + c];
        mx = fmaxf(mx, v);
        sm += v;
    }
    d_poolmax[(b * 8 + st) * FEAT + c] = mx;
    d_poolsum[(b * 8 + st) * FEAT + c] = sm;
}

// head: combine pooling, fc1 + LN + relu, fc2 + LN. One block per batch.
__global__ void head_kernel(const float* fc1_w, const float* fc1_b,
                            const float* ln1_g, const float* ln1_b,
                            const float* fc2_w, const float* fc2_b,
                            const float* ln2_g, const float* ln2_b,
                            float* out) {
    __shared__ float g[1024];
    __shared__ float h[512];
    __shared__ float red[256];
    __shared__ float red2[256];
    int b = blockIdx.x, tid = threadIdx.x;
    for (int c = tid; c < 512; c += 256) {
        float mx = -FLT_MAX, sm = 0.f;
        for (int st = 0; st < 8; st++) {
            mx = fmaxf(mx, d_poolmax[(b * 8 + st) * FEAT + c]);
            sm += d_poolsum[(b * 8 + st) * FEAT + c];
        }
        g[c] = mx;
        g[512 + c] = sm * (1.f / (float)N);
    }
    __syncthreads();
    for (int j = tid; j < 512; j += 256) {
        float acc = fc1_b[j];
        const float* wr = fc1_w + (size_t)j * 1024;
        for (int i = 0; i < 1024; i++) acc = fmaf(g[i], wr[i], acc);
        h[j] = acc;
    }
    __syncthreads();
    {
        float a = h[tid], bb = h[tid + 256];
        red[tid] = a + bb;
        red2[tid] = a * a + bb * bb;
    }
    __syncthreads();
    for (int s = 128; s > 0; s >>= 1) {
        if (tid < s) { red[tid] += red[tid + s]; red2[tid] += red2[tid + s]; }
        __syncthreads();
    }
    float mu = red[0] * (1.f / 512.f);
    float var = red2[0] * (1.f / 512.f) - mu * mu;
    float inv = rsqrtf(var + EPSV);
    __syncthreads();
    for (int j = tid; j < 512; j += 256)
        h[j] = fmaxf(0.f, (h[j] - mu) * inv * ln1_g[j] + ln1_b[j]);
    __syncthreads();
    float z = fc2_b[tid];
    {
        const float* wr = fc2_w + (size_t)tid * 512;
        for (int i = 0; i < 512; i++) z = fmaf(h[i], wr[i], z);
    }
    red[tid] = z;
    red2[tid] = z * z;
    __syncthreads();
    for (int s = 128; s > 0; s >>= 1) {
        if (tid < s) { red[tid] += red[tid + s]; red2[tid] += red2[tid + s]; }
        __syncthreads();
    }
    float mu2 = red[0] * (1.f / 256.f);
    float var2 = red2[0] * (1.f / 256.f) - mu2 * mu2;
    float inv2 = rsqrtf(var2 + EPSV);
    out[b * 256 + tid] = (z - mu2) * inv2 * ln2_g[tid] + ln2_b[tid];
}

// ---------------- launch ----------------

extern "C" void kernel_launch(void* const* d_in, const int* in_sizes, int n_in,
                              void* d_out, int out_size) {
    (void)in_sizes; (void)n_in; (void)out_size;
    const float* points = (const float*)d_in[0];
    const float* Wl[4]  = {(const float*)d_in[1], (const float*)d_in[4],
                           (const float*)d_in[7], (const float*)d_in[10]};
    const float* gl[4]  = {(const float*)d_in[2], (const float*)d_in[5],
                           (const float*)d_in[8], (const float*)d_in[11]};
    const float* bl[4]  = {(const float*)d_in[3], (const float*)d_in[6],
                           (const float*)d_in[9], (const float*)d_in[12]};
    const float* fc1_w = (const float*)d_in[13];
    const float* fc1_b = (const float*)d_in[14];
    const float* ln1_g = (const float*)d_in[15];
    const float* ln1_b = (const float*)d_in[16];
    const float* fc2_w = (const float*)d_in[17];
    const float* fc2_b = (const float*)d_in[18];
    const float* ln2_g = (const float*)d_in[19];
    const float* ln2_b = (const float*)d_in[20];

    const int Cs[4]     = {3, 64, 64, 128};
    const int Os[4]     = {64, 64, 128, 256};
    const int offin[4]  = {0, 0, 64, 128};
    const int offout[4] = {0, 64, 128, 256};

    for (int l = 0; l < 4; l++) {
        const float* xin = (l == 0) ? points : nullptr;   // nullptr -> d_feat inside kernels
        int stride = (l == 0) ? 3 : FEAT;
        int C = Cs[l], O = Os[l];

        zero_acc_kernel<<<1, 256>>>();
        xx_kernel<<<(PTS + 255) / 256, 256>>>(xin, stride, offin[l], C);
        dist_kernel<<<dim3(B, N / 128, N / 128), 256>>>(xin, stride, offin[l], C);
        select_kernel<<<PTS / 4, 128>>>();
        st_kernel<<<PTS / 32, O>>>(xin, stride, offin[l], C, O, Wl[l]);
        gather_kernel<<<PTS / 64, 256>>>(O);
        bn_kernel<<<1, O>>>(O, gl[l], bl[l]);
        apply_kernel<<<(PTS * O + 255) / 256, 256>>>(O, offout[l]);
    }

    pool_kernel<<<dim3(B, 8), 512>>>();
    head_kernel<<<B, 256>>>(fc1_w, fc1_b, ln1_g, ln1_b,
                            fc2_w, fc2_b, ln2_g, ln2_b, (float*)d_out);
}

// round 3
// speedup vs baseline: 2.1062x; 1.2574x over previous
#include <cuda_runtime.h>
#include <float.h>
#include <math.h>

#define B 8
#define N 2048
#define PTS (B*N)          // 16384
#define KNN 20
#define FEAT 512
#define OMAX 256
#define EPSV 1e-5f
#define NB 16              // N/128 tile count

// ---------------- scratch (static device allocations) ----------------
__device__ float d_dist[(size_t)PTS * N];        // 134 MB
__device__ float d_xx[PTS];
__device__ int   d_idx[PTS * KNN];
__device__ float d_feat[(size_t)PTS * FEAT];
__device__ float d_s[(size_t)PTS * OMAX];
__device__ float d_t[(size_t)PTS * OMAX];
__device__ float d_maxg[(size_t)PTS * OMAX];
__device__ float d_ming[(size_t)PTS * OMAX];
__device__ float d_acc_s[OMAX], d_acc_s2[OMAX], d_acc_cr[OMAX], d_acc_t[OMAX], d_acc_t2[OMAX];
__device__ float d_rho[OMAX], d_shift[OMAX];
__device__ float d_poolmax[B * 8 * FEAT], d_poolsum[B * 8 * FEAT];

// ---------------- kernels ----------------

__global__ void zero_acc_kernel() {
    int i = threadIdx.x;
    if (i < OMAX) {
        d_acc_s[i] = 0.f; d_acc_s2[i] = 0.f; d_acc_cr[i] = 0.f;
        d_acc_t[i] = 0.f; d_acc_t2[i] = 0.f;
    }
}

__global__ void xx_kernel(const float* x, int stride, int off, int C) {
    const float* xp = x ? x : d_feat;
    int p = blockIdx.x * blockDim.x + threadIdx.x;
    if (p >= PTS) return;
    const float* r = xp + (size_t)p * stride + off;
    float s = 0.f;
    for (int c = 0; c < C; c++) { float v = r[c]; s = fmaf(v, v, s); }
    d_xx[p] = s;
}

// dist: symmetric — only upper-tri 128x128 block pairs; mirror written transposed.
// smem tiles transposed [kk][row] for LDS.128 fragment loads.
__global__ void dist_kernel(const float* __restrict__ x, int stride, int off, int C) {
    const float* xp = x ? x : d_feat;
    int b = blockIdx.x;
    // map blockIdx.y -> (pi, pj), pi <= pj
    int p = blockIdx.y;
    int pi = 0;
    while (p >= NB - pi) { p -= NB - pi; pi++; }
    int pj = pi + p;
    int n0 = pi * 128, m0 = pj * 128;

    __shared__ float As[16][132];
    __shared__ float Bs[16][132];
    __shared__ float xn_s[128], xm_s[128];

    int tid = threadIdx.x;
    int tx = tid & 15, ty = tid >> 4;
    if (tid < 128) xn_s[tid] = d_xx[b * N + n0 + tid];
    else           xm_s[tid - 128] = d_xx[b * N + m0 + tid - 128];

    float acc[8][8];
#pragma unroll
    for (int i = 0; i < 8; i++)
#pragma unroll
        for (int j = 0; j < 8; j++) acc[i][j] = 0.f;

    bool diag = (pi == pj);
    for (int c0 = 0; c0 < C; c0 += 16) {
        for (int l = tid; l < 2048; l += 256) {
            int r = l >> 4, cc = l & 15;
            int c = c0 + cc;
            float av = 0.f;
            if (c < C) av = xp[(size_t)(b * N + n0 + r) * stride + off + c];
            As[cc][r] = av;
            if (!diag) {
                float bv = 0.f;
                if (c < C) bv = xp[(size_t)(b * N + m0 + r) * stride + off + c];
                Bs[cc][r] = bv;
            }
        }
        __syncthreads();
        const float (*Bp)[132] = diag ? As : Bs;
#pragma unroll
        for (int kk = 0; kk < 16; kk++) {
            float4 a0 = *(const float4*)&As[kk][ty * 4];
            float4 a1 = *(const float4*)&As[kk][64 + ty * 4];
            float4 b0 = *(const float4*)&Bp[kk][tx * 4];
            float4 b1 = *(const float4*)&Bp[kk][64 + tx * 4];
            float a[8] = {a0.x, a0.y, a0.z, a0.w, a1.x, a1.y, a1.z, a1.w};
            float bb[8] = {b0.x, b0.y, b0.z, b0.w, b1.x, b1.y, b1.z, b1.w};
#pragma unroll
            for (int i = 0; i < 8; i++)
#pragma unroll
                for (int j = 0; j < 8; j++) acc[i][j] = fmaf(a[i], bb[j], acc[i][j]);
        }
        __syncthreads();
    }

    // main tile write (rows n, cols m), float4 over m
#pragma unroll
    for (int i = 0; i < 8; i++) {
        int nl = (i < 4) ? (ty * 4 + i) : (64 + ty * 4 + i - 4);
        float xn = xn_s[nl];
        float* orow = d_dist + (size_t)(b * N + n0 + nl) * N + m0;
        float4 v0, v1;
        v0.x = xn + xm_s[tx * 4 + 0] - 2.f * acc[i][0];
        v0.y = xn + xm_s[tx * 4 + 1] - 2.f * acc[i][1];
        v0.z = xn + xm_s[tx * 4 + 2] - 2.f * acc[i][2];
        v0.w = xn + xm_s[tx * 4 + 3] - 2.f * acc[i][3];
        v1.x = xn + xm_s[64 + tx * 4 + 0] - 2.f * acc[i][4];
        v1.y = xn + xm_s[64 + tx * 4 + 1] - 2.f * acc[i][5];
        v1.z = xn + xm_s[64 + tx * 4 + 2] - 2.f * acc[i][6];
        v1.w = xn + xm_s[64 + tx * 4 + 3] - 2.f * acc[i][7];
        *(float4*)(orow + tx * 4) = v0;
        *(float4*)(orow + 64 + tx * 4) = v1;
    }
    if (!diag) {
        // mirror tile (rows m, cols n), float4 over n
#pragma unroll
        for (int j = 0; j < 8; j++) {
            int ml = (j < 4) ? (tx * 4 + j) : (64 + tx * 4 + j - 4);
            float xm = xm_s[ml];
            float* orow = d_dist + (size_t)(b * N + m0 + ml) * N + n0;
            float4 v0, v1;
            v0.x = xn_s[ty * 4 + 0] + xm - 2.f * acc[0][j];
            v0.y = xn_s[ty * 4 + 1] + xm - 2.f * acc[1][j];
            v0.z = xn_s[ty * 4 + 2] + xm - 2.f * acc[2][j];
            v0.w = xn_s[ty * 4 + 3] + xm - 2.f * acc[3][j];
            v1.x = xn_s[64 + ty * 4 + 0] + xm - 2.f * acc[4][j];
            v1.y = xn_s[64 + ty * 4 + 1] + xm - 2.f * acc[5][j];
            v1.z = xn_s[64 + ty * 4 + 2] + xm - 2.f * acc[6][j];
            v1.w = xn_s[64 + ty * 4 + 3] + xm - 2.f * acc[7][j];
            *(float4*)(orow + ty * 4) = v0;
            *(float4*)(orow + 64 + ty * 4) = v1;
        }
    }
}

// per-row top-KNN: warp per row; element i stored at rows[m][i&31], m=i>>5 (stride 33).
// per-lane cached strip min + warp shfl argmin; COOPERATIVE rescan of winner strip.
__global__ void select_kernel() {
    __shared__ float rows[4][64][33];
    int warp = threadIdx.x >> 5, lane = threadIdx.x & 31;
    int pt = blockIdx.x * 4 + warp;
    float (*row)[33] = rows[warp];
    const float4* dr4 = (const float4*)(d_dist + (size_t)pt * N);
#pragma unroll
    for (int it = 0; it < 16; it++) {
        int i4 = lane + 32 * it;            // float4 index
        float4 v = dr4[i4];
        int e = 4 * i4;
        row[e >> 5][e & 31] = v.x;
        row[(e + 1) >> 5][(e + 1) & 31] = v.y;
        row[(e + 2) >> 5][(e + 2) & 31] = v.z;
        row[(e + 3) >> 5][(e + 3) & 31] = v.w;
    }
    __syncwarp();

    // per-lane strip min: elements lane + 32*m  ->  row[m][lane]
    float bv = FLT_MAX; int bi = 0;
#pragma unroll 8
    for (int m = 0; m < 64; m++) {
        float v = row[m][lane];
        if (v < bv) { bv = v; bi = lane + 32 * m; }
    }
    int* ip = d_idx + pt * KNN;
    for (int sel = 0; sel < KNN; sel++) {
        float mv = bv; int mi = bi;
#pragma unroll
        for (int s = 16; s > 0; s >>= 1) {
            float ov = __shfl_xor_sync(0xffffffff, mv, s);
            int   oi = __shfl_xor_sync(0xffffffff, mi, s);
            if (ov < mv || (ov == mv && oi < mi)) { mv = ov; mi = oi; }
        }
        if (lane == 0) ip[sel] = mi;
        int ol = mi & 31;                   // owner lane
        if (lane == ol) row[mi >> 5][ol] = FLT_MAX;
        __syncwarp();
        // cooperative rescan of owner strip: lane handles m = lane, lane+32
        float v0 = row[lane][ol];
        float v1 = row[lane + 32][ol];
        float nv; int ni;
        if (v0 <= v1) { nv = v0; ni = ol + 32 * lane; }
        else          { nv = v1; ni = ol + 32 * (lane + 32); }
#pragma unroll
        for (int s = 16; s > 0; s >>= 1) {
            float ov = __shfl_xor_sync(0xffffffff, nv, s);
            int   oi = __shfl_xor_sync(0xffffffff, ni, s);
            if (ov < nv || (ov == nv && oi < ni)) { nv = ov; ni = oi; }
        }
        if (lane == ol) { bv = nv; bi = ni; }
        __syncwarp();
    }
}

// s = W1 . x ; t = (W2-W1) . x ; + sum(t), sum(t^2)
__global__ void st_kernel(const float* x, int stride, int off, int C, int O, const float* W) {
    const float* xp = x ? x : d_feat;
    __shared__ float xs[32 * 128];
    int pt0 = blockIdx.x * 32;
    int tid = threadIdx.x;
    for (int i = tid; i < 32 * C; i += O) {
        int p = i / C, c = i - p * C;
        xs[i] = xp[(size_t)(pt0 + p) * stride + off + c];
    }
    __syncthreads();
    float as[32], at[32];
#pragma unroll
    for (int p = 0; p < 32; p++) { as[p] = 0.f; at[p] = 0.f; }
    const float* wr = W + (size_t)tid * 2 * C;
    for (int c = 0; c < C; c++) {
        float w1 = wr[c];
        float wd = wr[C + c] - w1;
#pragma unroll
        for (int p = 0; p < 32; p++) {
            float xv = xs[p * C + c];
            as[p] = fmaf(w1, xv, as[p]);
            at[p] = fmaf(wd, xv, at[p]);
        }
    }
    float ts = 0.f, ts2 = 0.f;
#pragma unroll
    for (int p = 0; p < 32; p++) {
        size_t e = (size_t)(pt0 + p) * O + tid;
        d_s[e] = as[p];
        d_t[e] = at[p];
        ts += at[p];
        ts2 = fmaf(at[p], at[p], ts2);
    }
    atomicAdd(&d_acc_t[tid], ts);
    atomicAdd(&d_acc_t2[tid], ts2);
}

__global__ void gather_kernel(int O) {
    int w = threadIdx.x >> 5, lane = threadIdx.x & 31;
    int nchunks = O >> 5;
    int oc = w & (nchunks - 1);
    int sub = w / nchunks;
    int nsub = 8 / nchunks;
    int o = (oc << 5) + lane;
    int pt0 = blockIdx.x * 64;
    float sum = 0.f, sq = 0.f, cross = 0.f;
    for (int p = sub; p < 64; p += nsub) {
        int pt = pt0 + p;
        int b = pt >> 11;
        const int* ip = d_idx + pt * KNN;
        float psum = 0.f, psq = 0.f, pmx = -FLT_MAX, pmn = FLT_MAX;
#pragma unroll
        for (int k = 0; k < KNN; k++) {
            int m = ip[k];
            float v = d_s[(size_t)((b << 11) + m) * O + o];
            psum += v;
            psq = fmaf(v, v, psq);
            pmx = fmaxf(pmx, v);
            pmn = fminf(pmn, v);
        }
        float tv = d_t[(size_t)pt * O + o];
        sum += psum;
        sq += psq;
        cross = fmaf(tv, psum, cross);
        d_maxg[(size_t)pt * O + o] = pmx;
        d_ming[(size_t)pt * O + o] = pmn;
    }
    atomicAdd(&d_acc_s[o], sum);
    atomicAdd(&d_acc_s2[o], sq);
    atomicAdd(&d_acc_cr[o], cross);
}

__global__ void bn_kernel(int O, const float* gamma, const float* beta) {
    int o = threadIdx.x;
    if (o >= O) return;
    const float cnt = (float)PTS * (float)KNN;
    float mean = (d_acc_s[o] + (float)KNN * d_acc_t[o]) / cnt;
    float e2 = (d_acc_s2[o] + 2.f * d_acc_cr[o] + (float)KNN * d_acc_t2[o]) / cnt;
    float var = e2 - mean * mean;
    float inv = rsqrtf(var + EPSV);
    float rho = gamma[o] * inv;
    d_rho[o] = rho;
    d_shift[o] = beta[o] - mean * rho;
}

__global__ void apply_kernel(int O, int off) {
    int e = blockIdx.x * 256 + threadIdx.x;
    if (e >= PTS * O) return;
    int o = e % O;
    int pt = e / O;
    float r = d_rho[o];
    float base = d_t[e] + (r >= 0.f ? d_maxg[e] : d_ming[e]);
    float res = fmaf(r, base, d_shift[o]);
    d_feat[(size_t)pt * FEAT + off + o] = fmaxf(res, 0.f);
}

__global__ void pool_kernel() {
    int b = blockIdx.x, st = blockIdx.y;
    int c = threadIdx.x;
    float mx = -FLT_MAX, sm = 0.f;
    int n0 = st * 256;
    for (int n = n0; n < n0 + 256; n++) {
        float v = d_feat[(size_t)(b * N + n) * FEAT + c];
        mx = fmaxf(mx, v);
        sm += v;
    }
    d_poolmax[(b * 8 + st) * FEAT + c] = mx;
    d_poolsum[(b * 8 + st) * FEAT + c] = sm;
}

__global__ void head_kernel(const float* fc1_w, const float* fc1_b,
                            const float* ln1_g, const float* ln1_b,
                            const float* fc2_w, const float* fc2_b,
                            const float* ln2_g, const float* ln2_b,
                            float* out) {
    __shared__ float g[1024];
    __shared__ float h[512];
    __shared__ float red[256];
    __shared__ float red2[256];
    int b = blockIdx.x, tid = threadIdx.x;
    for (int c = tid; c < 512; c += 256) {
        float mx = -FLT_MAX, sm = 0.f;
        for (int st = 0; st < 8; st++) {
            mx = fmaxf(mx, d_poolmax[(b * 8 + st) * FEAT + c]);
            sm += d_poolsum[(b * 8 + st) * FEAT + c];
        }
        g[c] = mx;
        g[512 + c] = sm * (1.f / (float)N);
    }
    __syncthreads();
    for (int j = tid; j < 512; j += 256) {
        float acc = fc1_b[j];
        const float* wr = fc1_w + (size_t)j * 1024;
        for (int i = 0; i < 1024; i++) acc = fmaf(g[i], wr[i], acc);
        h[j] = acc;
    }
    __syncthreads();
    {
        float a = h[tid], bb = h[tid + 256];
        red[tid] = a + bb;
        red2[tid] = a * a + bb * bb;
    }
    __syncthreads();
    for (int s = 128; s > 0; s >>= 1) {
        if (tid < s) { red[tid] += red[tid + s]; red2[tid] += red2[tid + s]; }
        __syncthreads();
    }
    float mu = red[0] * (1.f / 512.f);
    float var = red2[0] * (1.f / 512.f) - mu * mu;
    float inv = rsqrtf(var + EPSV);
    __syncthreads();
    for (int j = tid; j < 512; j += 256)
        h[j] = fmaxf(0.f, (h[j] - mu) * inv * ln1_g[j] + ln1_b[j]);
    __syncthreads();
    float z = fc2_b[tid];
    {
        const float* wr = fc2_w + (size_t)tid * 512;
        for (int i = 0; i < 512; i++) z = fmaf(h[i], wr[i], z);
    }
    red[tid] = z;
    red2[tid] = z * z;
    __syncthreads();
    for (int s = 128; s > 0; s >>= 1) {
        if (tid < s) { red[tid] += red[tid + s]; red2[tid] += red2[tid + s]; }
        __syncthreads();
    }
    float mu2 = red[0] * (1.f / 256.f);
    float var2 = red2[0] * (1.f / 256.f) - mu2 * mu2;
    float inv2 = rsqrtf(var2 + EPSV);
    out[b * 256 + tid] = (z - mu2) * inv2 * ln2_g[tid] + ln2_b[tid];
}

// ---------------- launch ----------------

extern "C" void kernel_launch(void* const* d_in, const int* in_sizes, int n_in,
                              void* d_out, int out_size) {
    (void)in_sizes; (void)n_in; (void)out_size;
    const float* points = (const float*)d_in[0];
    const float* Wl[4]  = {(const float*)d_in[1], (const float*)d_in[4],
                           (const float*)d_in[7], (const float*)d_in[10]};
    const float* gl[4]  = {(const float*)d_in[2], (const float*)d_in[5],
                           (const float*)d_in[8], (const float*)d_in[11]};
    const float* bl[4]  = {(const float*)d_in[3], (const float*)d_in[6],
                           (const float*)d_in[9], (const float*)d_in[12]};
    const float* fc1_w = (const float*)d_in[13];
    const float* fc1_b = (const float*)d_in[14];
    const float* ln1_g = (const float*)d_in[15];
    const float* ln1_b = (const float*)d_in[16];
    const float* fc2_w = (const float*)d_in[17];
    const float* fc2_b = (const float*)d_in[18];
    const float* ln2_g = (const float*)d_in[19];
    const float* ln2_b = (const float*)d_in[20];

    const int Cs[4]     = {3, 64, 64, 128};
    const int Os[4]     = {64, 64, 128, 256};
    const int offin[4]  = {0, 0, 64, 128};
    const int offout[4] = {0, 64, 128, 256};
    const int NPAIRS = NB * (NB + 1) / 2;   // 136

    for (int l = 0; l < 4; l++) {
        const float* xin = (l == 0) ? points : nullptr;
        int stride = (l == 0) ? 3 : FEAT;
        int C = Cs[l], O = Os[l];

        zero_acc_kernel<<<1, 256>>>();
        xx_kernel<<<(PTS + 255) / 256, 256>>>(xin, stride, offin[l], C);
        dist_kernel<<<dim3(B, NPAIRS), 256>>>(xin, stride, offin[l], C);
        select_kernel<<<PTS / 4, 128>>>();
        st_kernel<<<PTS / 32, O>>>(xin, stride, offin[l], C, O, Wl[l]);
        gather_kernel<<<PTS / 64, 256>>>(O);
        bn_kernel<<<1, O>>>(O, gl[l], bl[l]);
        apply_kernel<<<(PTS * O + 255) / 256, 256>>>(O, offout[l]);
    }

    pool_kernel<<<dim3(B, 8), 512>>>();
    head_kernel<<<B, 256>>>(fc1_w, fc1_b, ln1_g, ln1_b,
                            fc2_w, fc2_b, ln2_g, ln2_b, (float*)d_out);
}